// round 3
// baseline (speedup 1.0000x reference)
#include <cuda_runtime.h>

#define BATCH  16
#define HH     128
#define WW     128
#define HIDDEN 16
#define KS     9
#define PAD    4
#define NBLK   50
#define NCH_MAX (NBLK + 1)   // 51 feature channels max (x + 50 outputs)

// Persistent feature stack: [channel][batch][h][w], channel 0 = x, channel 1+i = y_i
__device__ float g_feats[(size_t)NCH_MAX * BATCH * HH * WW];

// ---- packed f32x2 helpers (Blackwell: 2 fp32 FMAs per instruction) ----
__device__ __forceinline__ unsigned long long pack2(float lo, float hi) {
    unsigned long long r;
    asm("mov.b64 %0, {%1, %2};" : "=l"(r) : "f"(lo), "f"(hi));
    return r;
}
__device__ __forceinline__ void unpack2(unsigned long long v, float& lo, float& hi) {
    asm("mov.b64 {%0, %1}, %2;" : "=f"(lo), "=f"(hi) : "l"(v));
}
__device__ __forceinline__ unsigned long long ffma2(unsigned long long a,
                                                    unsigned long long b,
                                                    unsigned long long c) {
    unsigned long long d;
    asm("fma.rn.f32x2 %0, %1, %2, %3;" : "=l"(d) : "l"(a), "l"(b), "l"(c));
    return d;
}

// Tile: 32x32 output pixels per CTA, 256 threads (32 wide x 8), 4 rows per thread.
#define TW  32
#define TH  32
#define ITW (TW + 2 * PAD)   // 40
#define ITH (TH + 2 * PAD)   // 40

__global__ __launch_bounds__(256, 1) void dense_block_kernel(
    const float* __restrict__ w1,   // [NBLK][HIDDEN][NCH_MAX][9][9]
    const float* __restrict__ b1,   // [NBLK][HIDDEN]
    const float* __restrict__ w2,   // [NBLK][HIDDEN]
    const float* __restrict__ b2,   // [NBLK]
    float* __restrict__ out,        // [BATCH][NBLK][HH][WW]
    int blk)
{
    __shared__ __align__(16) float s_in[ITH * ITW];        // 40*40 = 1600 floats
    __shared__ __align__(16) float s_w[KS * KS * HIDDEN];  // [tap][oc], 81*16

    const int tx     = threadIdx.x & 31;
    const int ty     = threadIdx.x >> 5;        // 0..7
    const int tile_x = blockIdx.x * TW;
    const int tile_y = blockIdx.y * TH;
    const int b      = blockIdx.z;
    const int nch    = blk + 1;

    // Accumulators: 4 pixel-rows x 8 oc-pairs, packed f32x2
    unsigned long long acc[4][8];
    #pragma unroll
    for (int r = 0; r < 4; ++r)
        #pragma unroll
        for (int p = 0; p < 8; ++p) acc[r][p] = 0ull;

    const float* w1blk = w1 + (size_t)blk * HIDDEN * NCH_MAX * (KS * KS);

    for (int c = 0; c < nch; ++c) {
        __syncthreads();  // protect smem from previous iteration's readers

        // Cooperative load of 40x40 halo tile for input channel c (zero-padded)
        const float* fch = g_feats + ((size_t)c * BATCH + b) * (HH * WW);
        for (int idx = threadIdx.x; idx < ITH * ITW; idx += 256) {
            int r  = idx / ITW;
            int cc = idx - r * ITW;
            int gy = tile_y + r - PAD;
            int gx = tile_x + cc - PAD;
            float v = 0.0f;
            if ((unsigned)gy < (unsigned)HH && (unsigned)gx < (unsigned)WW)
                v = fch[gy * WW + gx];
            s_in[idx] = v;
        }
        // Repack weights: s_w[tap*16 + oc] = w1[blk][oc][c][tap]
        const float* wc = w1blk + (size_t)c * (KS * KS);
        for (int idx = threadIdx.x; idx < HIDDEN * KS * KS; idx += 256) {
            int oc  = idx / (KS * KS);
            int tap = idx - oc * (KS * KS);
            s_w[tap * HIDDEN + oc] = wc[(size_t)oc * (NCH_MAX * KS * KS) + tap];
        }
        __syncthreads();

        #pragma unroll 1   // keep loop body inside I$ (body ~7KB when kw unrolled)
        for (int kh = 0; kh < KS; ++kh) {
            const float* r0 = s_in + (ty + kh) * ITW + tx;
            #pragma unroll
            for (int kw = 0; kw < KS; ++kw) {
                // 8 broadcast LDS.64: weights for oc-pairs at this tap
                const unsigned long long* wp =
                    (const unsigned long long*)(s_w + (kh * KS + kw) * HIDDEN);
                unsigned long long wr[8];
                #pragma unroll
                for (int p = 0; p < 8; ++p) wr[p] = wp[p];
                #pragma unroll
                for (int r = 0; r < 4; ++r) {
                    float v = r0[r * 8 * ITW + kw];
                    unsigned long long vp = pack2(v, v);
                    #pragma unroll
                    for (int p = 0; p < 8; ++p)
                        acc[r][p] = ffma2(vp, wr[p], acc[r][p]);
                }
            }
        }
    }

    // Epilogue: bias + ReLU + 1x1 projection + sigmoid, write out + new feat channel
    float b1r[HIDDEN], w2r[HIDDEN];
    #pragma unroll
    for (int oc = 0; oc < HIDDEN; ++oc) {
        b1r[oc] = __ldg(&b1[blk * HIDDEN + oc]);
        w2r[oc] = __ldg(&w2[blk * HIDDEN + oc]);
    }
    const float b2v = __ldg(&b2[blk]);

    #pragma unroll
    for (int r = 0; r < 4; ++r) {
        float s = b2v;
        #pragma unroll
        for (int p = 0; p < 8; ++p) {
            float a, bb;
            unpack2(acc[r][p], a, bb);
            s += fmaxf(a + b1r[2 * p], 0.0f) * w2r[2 * p];
            s += fmaxf(bb + b1r[2 * p + 1], 0.0f) * w2r[2 * p + 1];
        }
        float y = 1.0f / (1.0f + __expf(-s));
        int h = tile_y + ty + 8 * r;
        int w = tile_x + tx;
        out[(((size_t)b * NBLK + blk) * HH + h) * WW + w] = y;
        g_feats[(((size_t)(blk + 1) * BATCH + b) * HH + h) * WW + w] = y;
    }
}

__global__ void copy_x_kernel(const float* __restrict__ x) {
    int i = blockIdx.x * blockDim.x + threadIdx.x;
    g_feats[i] = x[i];   // channel 0 layout [b][h][w] matches x (B,1,H,W)
}

extern "C" void kernel_launch(void* const* d_in, const int* in_sizes, int n_in,
                              void* d_out, int out_size) {
    const float* x  = (const float*)d_in[0];
    const float* w1 = (const float*)d_in[1];
    const float* b1 = (const float*)d_in[2];
    const float* w2 = (const float*)d_in[3];
    const float* b2 = (const float*)d_in[4];
    float* out = (float*)d_out;

    copy_x_kernel<<<(BATCH * HH * WW) / 256, 256>>>(x);

    dim3 grid(WW / TW, HH / TH, BATCH);  // 4 x 4 x 16 = 256 CTAs
    for (int i = 0; i < NBLK; ++i)
        dense_block_kernel<<<grid, 256>>>(w1, b1, w2, b2, out, i);
}

// round 4
// speedup vs baseline: 1.0008x; 1.0008x over previous
#include <cuda_runtime.h>

#define BATCH  16
#define HH     128
#define WW     128
#define HIDDEN 16
#define KS     9
#define PAD    4
#define NBLK   50
#define NCH_MAX (NBLK + 1)   // 51 feature channels max (x + 50 outputs)

// Persistent feature stack: [channel][batch][h][w], channel 0 = x, channel 1+i = y_i
__device__ float g_feats[(size_t)NCH_MAX * BATCH * HH * WW];

// ---- packed f32x2 helpers (Blackwell: 2 fp32 FMAs per instruction) ----
__device__ __forceinline__ unsigned long long pack2(float lo, float hi) {
    unsigned long long r;
    asm("mov.b64 %0, {%1, %2};" : "=l"(r) : "f"(lo), "f"(hi));
    return r;
}
__device__ __forceinline__ void unpack2(unsigned long long v, float& lo, float& hi) {
    asm("mov.b64 {%0, %1}, %2;" : "=f"(lo), "=f"(hi) : "l"(v));
}
__device__ __forceinline__ unsigned long long ffma2(unsigned long long a,
                                                    unsigned long long b,
                                                    unsigned long long c) {
    unsigned long long d;
    asm("fma.rn.f32x2 %0, %1, %2, %3;" : "=l"(d) : "l"(a), "l"(b), "l"(c));
    return d;
}

// Tile: 32x32 output pixels per CTA, 256 threads (32 wide x 8), 4 rows per thread.
#define TW  32
#define TH  32
#define ITW (TW + 2 * PAD)   // 40
#define ITH (TH + 2 * PAD)   // 40

__global__ __launch_bounds__(256, 1) void dense_block_kernel(
    const float* __restrict__ w1,   // [NBLK][HIDDEN][NCH_MAX][9][9]
    const float* __restrict__ b1,   // [NBLK][HIDDEN]
    const float* __restrict__ w2,   // [NBLK][HIDDEN]
    const float* __restrict__ b2,   // [NBLK]
    float* __restrict__ out,        // [BATCH][NBLK][HH][WW]
    int blk)
{
    __shared__ __align__(16) float s_in[ITH * ITW];        // 40*40 = 1600 floats
    __shared__ __align__(16) float s_w[KS * KS * HIDDEN];  // [tap][oc], 81*16

    const int tx     = threadIdx.x & 31;
    const int ty     = threadIdx.x >> 5;        // 0..7
    const int tile_x = blockIdx.x * TW;
    const int tile_y = blockIdx.y * TH;
    const int b      = blockIdx.z;
    const int nch    = blk + 1;

    // Accumulators: 4 pixel-rows x 8 oc-pairs, packed f32x2
    unsigned long long acc[4][8];
    #pragma unroll
    for (int r = 0; r < 4; ++r)
        #pragma unroll
        for (int p = 0; p < 8; ++p) acc[r][p] = 0ull;

    const float* w1blk = w1 + (size_t)blk * HIDDEN * NCH_MAX * (KS * KS);

    for (int c = 0; c < nch; ++c) {
        __syncthreads();  // protect smem from previous iteration's readers

        // Cooperative load of 40x40 halo tile for input channel c (zero-padded)
        const float* fch = g_feats + ((size_t)c * BATCH + b) * (HH * WW);
        for (int idx = threadIdx.x; idx < ITH * ITW; idx += 256) {
            int r  = idx / ITW;
            int cc = idx - r * ITW;
            int gy = tile_y + r - PAD;
            int gx = tile_x + cc - PAD;
            float v = 0.0f;
            if ((unsigned)gy < (unsigned)HH && (unsigned)gx < (unsigned)WW)
                v = fch[gy * WW + gx];
            s_in[idx] = v;
        }
        // Repack weights: s_w[tap*16 + oc] = w1[blk][oc][c][tap]
        const float* wc = w1blk + (size_t)c * (KS * KS);
        for (int idx = threadIdx.x; idx < HIDDEN * KS * KS; idx += 256) {
            int oc  = idx / (KS * KS);
            int tap = idx - oc * (KS * KS);
            s_w[tap * HIDDEN + oc] = wc[(size_t)oc * (NCH_MAX * KS * KS) + tap];
        }
        __syncthreads();

        #pragma unroll 1   // keep loop body inside I$ (body ~7KB when kw unrolled)
        for (int kh = 0; kh < KS; ++kh) {
            const float* r0 = s_in + (ty + kh) * ITW + tx;
            #pragma unroll
            for (int kw = 0; kw < KS; ++kw) {
                // 8 broadcast LDS.64: weights for oc-pairs at this tap
                const unsigned long long* wp =
                    (const unsigned long long*)(s_w + (kh * KS + kw) * HIDDEN);
                unsigned long long wr[8];
                #pragma unroll
                for (int p = 0; p < 8; ++p) wr[p] = wp[p];
                #pragma unroll
                for (int r = 0; r < 4; ++r) {
                    float v = r0[r * 8 * ITW + kw];
                    unsigned long long vp = pack2(v, v);
                    #pragma unroll
                    for (int p = 0; p < 8; ++p)
                        acc[r][p] = ffma2(vp, wr[p], acc[r][p]);
                }
            }
        }
    }

    // Epilogue: bias + ReLU + 1x1 projection + sigmoid, write out + new feat channel
    float b1r[HIDDEN], w2r[HIDDEN];
    #pragma unroll
    for (int oc = 0; oc < HIDDEN; ++oc) {
        b1r[oc] = __ldg(&b1[blk * HIDDEN + oc]);
        w2r[oc] = __ldg(&w2[blk * HIDDEN + oc]);
    }
    const float b2v = __ldg(&b2[blk]);

    #pragma unroll
    for (int r = 0; r < 4; ++r) {
        float s = b2v;
        #pragma unroll
        for (int p = 0; p < 8; ++p) {
            float a, bb;
            unpack2(acc[r][p], a, bb);
            s += fmaxf(a + b1r[2 * p], 0.0f) * w2r[2 * p];
            s += fmaxf(bb + b1r[2 * p + 1], 0.0f) * w2r[2 * p + 1];
        }
        float y = 1.0f / (1.0f + __expf(-s));
        int h = tile_y + ty + 8 * r;
        int w = tile_x + tx;
        out[(((size_t)b * NBLK + blk) * HH + h) * WW + w] = y;
        g_feats[(((size_t)(blk + 1) * BATCH + b) * HH + h) * WW + w] = y;
    }
}

__global__ void copy_x_kernel(const float* __restrict__ x) {
    int i = blockIdx.x * blockDim.x + threadIdx.x;
    g_feats[i] = x[i];   // channel 0 layout [b][h][w] matches x (B,1,H,W)
}

extern "C" void kernel_launch(void* const* d_in, const int* in_sizes, int n_in,
                              void* d_out, int out_size) {
    const float* x  = (const float*)d_in[0];
    const float* w1 = (const float*)d_in[1];
    const float* b1 = (const float*)d_in[2];
    const float* w2 = (const float*)d_in[3];
    const float* b2 = (const float*)d_in[4];
    float* out = (float*)d_out;

    copy_x_kernel<<<(BATCH * HH * WW) / 256, 256>>>(x);

    dim3 grid(WW / TW, HH / TH, BATCH);  // 4 x 4 x 16 = 256 CTAs
    for (int i = 0; i < NBLK; ++i)
        dense_block_kernel<<<grid, 256>>>(w1, b1, w2, b2, out, i);
}